// round 7
// baseline (speedup 1.0000x reference)
#include <cuda_runtime.h>
#include <cuda_bf16.h>

#define TTOK 27648
#define CDIM 512
#define PIT 65

// Scratch (__device__ globals; no allocation APIs allowed)
__device__ float g_X[TTOK * CDIM];          // activations / attention output
__device__ float g_QKV[TTOK * 3 * CDIM];    // Q,K,V (or fused qkv for branch 3)

// ---------------------------------------------------------------------------
// Gather/transpose: out[(m*J + j)*512 + c] = x[m*CJ + c*J + j]
// grid (ceil(J/32), 16, M), block (32,32)
// ---------------------------------------------------------------------------
__global__ void transpose_gather(const float* __restrict__ x, float* __restrict__ out,
                                 int J, int CJ)
{
    __shared__ float sm[32][33];
    const int j0 = blockIdx.x * 32;
    const int c0 = blockIdx.y * 32;
    const int m  = blockIdx.z;
    const int tx = threadIdx.x, ty = threadIdx.y;
    if (j0 + tx < J)
        sm[ty][tx] = x[(size_t)m * CJ + (size_t)(c0 + ty) * J + (j0 + tx)];
    __syncthreads();
    if (j0 + ty < J)
        out[(size_t)(m * J + j0 + ty) * CDIM + c0 + tx] = sm[tx][ty];
}

// ---------------------------------------------------------------------------
// SGEMM: C[M,N] = A[M,K] @ B[K,N] (+ bias) (+= if accum)
// 128x128 tile, k-slice 8, double buffered, 256 threads, 8x8 per thread.
// Requires M%128==0, N%128==0, K%8==0.
// ---------------------------------------------------------------------------
__global__ __launch_bounds__(256)
void sgemm(const float* __restrict__ A, const float* __restrict__ Bw,
           const float* __restrict__ bias, float* __restrict__ C,
           int M, int N, int K, int accum)
{
    __shared__ float As[2][8][128];
    __shared__ float Bs[2][8][128];
    const int tid = threadIdx.x;
    const int bx = blockIdx.x, by = blockIdx.y;
    const int tx = tid & 15, ty = tid >> 4;
    const int arow = tid >> 1, acol = (tid & 1) << 2;
    const int brow = tid >> 5, bcol = (tid & 31) << 2;

    const float* Ap = A + (size_t)(by * 128 + arow) * K + acol;
    const float* Bp = Bw + (size_t)brow * N + bx * 128 + bcol;

    float acc[8][8];
#pragma unroll
    for (int i = 0; i < 8; i++)
#pragma unroll
        for (int j = 0; j < 8; j++) acc[i][j] = 0.f;

    float4 a4 = *(const float4*)Ap;
    float4 b4 = *(const float4*)Bp;
    As[0][acol + 0][arow] = a4.x;
    As[0][acol + 1][arow] = a4.y;
    As[0][acol + 2][arow] = a4.z;
    As[0][acol + 3][arow] = a4.w;
    *(float4*)&Bs[0][brow][bcol] = b4;
    __syncthreads();

    const int nk = K >> 3;
    for (int kt = 0; kt < nk; kt++) {
        const int cur = kt & 1;
        float4 a4n, b4n;
        if (kt + 1 < nk) {
            a4n = *(const float4*)(Ap + (kt + 1) * 8);
            b4n = *(const float4*)(Bp + (size_t)(kt + 1) * 8 * N);
        }
#pragma unroll
        for (int k = 0; k < 8; k++) {
            float4 a0 = *(const float4*)&As[cur][k][ty * 4];
            float4 a1 = *(const float4*)&As[cur][k][64 + ty * 4];
            float4 b0 = *(const float4*)&Bs[cur][k][tx * 4];
            float4 b1 = *(const float4*)&Bs[cur][k][64 + tx * 4];
            float av[8] = {a0.x, a0.y, a0.z, a0.w, a1.x, a1.y, a1.z, a1.w};
            float bv[8] = {b0.x, b0.y, b0.z, b0.w, b1.x, b1.y, b1.z, b1.w};
#pragma unroll
            for (int i = 0; i < 8; i++)
#pragma unroll
                for (int j = 0; j < 8; j++) acc[i][j] += av[i] * bv[j];
        }
        if (kt + 1 < nk) {
            const int nxt = cur ^ 1;
            As[nxt][acol + 0][arow] = a4n.x;
            As[nxt][acol + 1][arow] = a4n.y;
            As[nxt][acol + 2][arow] = a4n.z;
            As[nxt][acol + 3][arow] = a4n.w;
            *(float4*)&Bs[nxt][brow][bcol] = b4n;
        }
        __syncthreads();
    }

    float bb[8];
#pragma unroll
    for (int j = 0; j < 8; j++) {
        int cc = bx * 128 + ((j < 4) ? tx * 4 + j : 64 + tx * 4 + (j - 4));
        bb[j] = bias ? bias[cc] : 0.f;
    }
#pragma unroll
    for (int i = 0; i < 8; i++) {
        int r = by * 128 + ((i < 4) ? ty * 4 + i : 64 + ty * 4 + (i - 4));
        float* Cr = C + (size_t)r * N + bx * 128;
        float4 v0 = make_float4(acc[i][0] + bb[0], acc[i][1] + bb[1],
                                acc[i][2] + bb[2], acc[i][3] + bb[3]);
        float4 v1 = make_float4(acc[i][4] + bb[4], acc[i][5] + bb[5],
                                acc[i][6] + bb[6], acc[i][7] + bb[7]);
        if (accum) {
            float4 o0 = *(const float4*)&Cr[tx * 4];
            float4 o1 = *(const float4*)&Cr[64 + tx * 4];
            v0.x += o0.x; v0.y += o0.y; v0.z += o0.z; v0.w += o0.w;
            v1.x += o1.x; v1.y += o1.y; v1.z += o1.z; v1.w += o1.w;
        }
        *(float4*)&Cr[tx * 4] = v0;
        *(float4*)&Cr[64 + tx * 4] = v1;
    }
}

// ---------------------------------------------------------------------------
// Branch-1 attention: seq = ntile*64, head dim 64, flash online softmax.
// grid (ntile, 8, nbatch), 256 threads, 4x4 register tile per thread.
// ---------------------------------------------------------------------------
__global__ __launch_bounds__(256)
void attn_long(const float* __restrict__ Q, const float* __restrict__ K,
               const float* __restrict__ V, float* __restrict__ O, int ntile)
{
    extern __shared__ float sm[];
    float* Qs   = sm;                 // 64*65
    float* Ks   = Qs + 64 * PIT;
    float* Vs   = Ks + 64 * PIT;
    float* Ss   = Vs + 64 * PIT;
    float* rowm = Ss + 64 * PIT;      // 64
    float* rowl = rowm + 64;          // 64
    float* corr = rowl + 64;          // 64
    float* red  = corr + 64;          // 16*64

    const int tid = threadIdx.x;
    const int qt = blockIdx.x, h = blockIdx.y, bat = blockIdx.z;
    const int seq = ntile * 64;
    const size_t base = (size_t)bat * seq;
    const int hoff = h * 64;
    const int tr = tid >> 4, tc = tid & 15;

    for (int p = tid; p < 1024; p += 256) {
        int r = p >> 4, c = (p & 15) << 2;
        float4 v = *(const float4*)&Q[(base + qt * 64 + r) * CDIM + hoff + c];
        float* q = &Qs[r * PIT + c];
        q[0] = v.x; q[1] = v.y; q[2] = v.z; q[3] = v.w;
    }
    if (tid < 64) { rowm[tid] = -1e30f; rowl[tid] = 0.f; }

    float o[4][4];
#pragma unroll
    for (int i = 0; i < 4; i++)
#pragma unroll
        for (int j = 0; j < 4; j++) o[i][j] = 0.f;

    for (int kt = 0; kt < ntile; kt++) {
        __syncthreads();
        for (int p = tid; p < 1024; p += 256) {
            int r = p >> 4, c = (p & 15) << 2;
            size_t row = base + kt * 64 + r;
            float4 k4 = *(const float4*)&K[row * CDIM + hoff + c];
            float* ks = &Ks[r * PIT + c];
            ks[0] = k4.x; ks[1] = k4.y; ks[2] = k4.z; ks[3] = k4.w;
            float4 v4 = *(const float4*)&V[row * CDIM + hoff + c];
            float* vs = &Vs[r * PIT + c];
            vs[0] = v4.x; vs[1] = v4.y; vs[2] = v4.z; vs[3] = v4.w;
        }
        __syncthreads();

        float s4[4][4];
#pragma unroll
        for (int i = 0; i < 4; i++)
#pragma unroll
            for (int j = 0; j < 4; j++) s4[i][j] = 0.f;
#pragma unroll 8
        for (int k = 0; k < 64; k++) {
            float qv[4], kv[4];
#pragma unroll
            for (int i = 0; i < 4; i++) qv[i] = Qs[(tr * 4 + i) * PIT + k];
#pragma unroll
            for (int j = 0; j < 4; j++) kv[j] = Ks[(tc * 4 + j) * PIT + k];
#pragma unroll
            for (int i = 0; i < 4; i++)
#pragma unroll
                for (int j = 0; j < 4; j++) s4[i][j] += qv[i] * kv[j];
        }
#pragma unroll
        for (int i = 0; i < 4; i++) {
            float m = -1e30f;
#pragma unroll
            for (int j = 0; j < 4; j++) {
                s4[i][j] *= 0.125f;
                m = fmaxf(m, s4[i][j]);
            }
            red[tc * 64 + tr * 4 + i] = m;
        }
        __syncthreads();
        if (tid < 64) {
            float m = red[tid];
#pragma unroll
            for (int t2 = 1; t2 < 16; t2++) m = fmaxf(m, red[t2 * 64 + tid]);
            float mo = rowm[tid];
            float mn = fmaxf(mo, m);
            rowm[tid] = mn;
            corr[tid] = __expf(mo - mn);
        }
        __syncthreads();
#pragma unroll
        for (int i = 0; i < 4; i++) {
            int r = tr * 4 + i;
            float mn = rowm[r];
            float l = 0.f;
#pragma unroll
            for (int j = 0; j < 4; j++) {
                float p = __expf(s4[i][j] - mn);
                Ss[r * PIT + tc * 4 + j] = p;
                l += p;
            }
            red[tc * 64 + r] = l;
        }
        __syncthreads();
        if (tid < 64) {
            float l = 0.f;
#pragma unroll
            for (int t2 = 0; t2 < 16; t2++) l += red[t2 * 64 + tid];
            rowl[tid] = rowl[tid] * corr[tid] + l;
        }
#pragma unroll
        for (int i = 0; i < 4; i++) {
            float cf = corr[tr * 4 + i];
#pragma unroll
            for (int j = 0; j < 4; j++) o[i][j] *= cf;
        }
#pragma unroll 8
        for (int k = 0; k < 64; k++) {
            float pv[4], vv[4];
#pragma unroll
            for (int i = 0; i < 4; i++) pv[i] = Ss[(tr * 4 + i) * PIT + k];
#pragma unroll
            for (int j = 0; j < 4; j++) vv[j] = Vs[k * PIT + tc * 4 + j];
#pragma unroll
            for (int i = 0; i < 4; i++)
#pragma unroll
                for (int j = 0; j < 4; j++) o[i][j] += pv[i] * vv[j];
        }
    }
    __syncthreads();
#pragma unroll
    for (int i = 0; i < 4; i++) {
        int r = tr * 4 + i;
        float inv = 1.f / rowl[r];
        float4 ov = make_float4(o[i][0] * inv, o[i][1] * inv, o[i][2] * inv, o[i][3] * inv);
        *(float4*)&O[(base + qt * 64 + r) * CDIM + hoff + tc * 4] = ov;
    }
}

// ---------------------------------------------------------------------------
// Branch-3 window attention: 64 tokens/window, rel-pos bias, exact softmax.
// grid (216, 8, 2), 256 threads. QKV fused with row stride 1536.
// ---------------------------------------------------------------------------
__global__ __launch_bounds__(256)
void attn_win(const float* __restrict__ QKV, float* __restrict__ O,
              const float* __restrict__ pos)
{
    extern __shared__ float sm[];
    float* Qs   = sm;
    float* Ks   = Qs + 64 * PIT;
    float* Vs   = Ks + 64 * PIT;
    float* Ss   = Vs + 64 * PIT;
    float* rowm = Ss + 64 * PIT;    // 64
    float* rowl = rowm + 64;        // 64
    float* red  = rowl + 64;        // 16*64
    float* ps   = red + 1024;       // 343
    __shared__ int rowIdx[64];

    const int tid = threadIdx.x;
    const int wi = blockIdx.x, h = blockIdx.y, b = blockIdx.z;
    const int hoff = h * 64;

    if (tid < 64) {
        const int whi = wi / 36, wwi = (wi / 6) % 6, wdi = wi % 6;
        int a = tid >> 4, b2 = (tid >> 2) & 3, c2 = tid & 3;
        int s = (whi * 4 + a) * 576 + (wwi * 4 + b2) * 24 + (wdi * 4 + c2);
        rowIdx[tid] = b * 13824 + s;
    }
    for (int p = tid; p < 343; p += 256) ps[p] = pos[p];
    __syncthreads();

    for (int p = tid; p < 1024; p += 256) {
        int r = p >> 4, c = (p & 15) << 2;
        const float* src = QKV + (size_t)rowIdx[r] * 1536 + hoff + c;
        float4 q4 = *(const float4*)(src);
        float4 k4 = *(const float4*)(src + 512);
        float4 v4 = *(const float4*)(src + 1024);
        float* q = &Qs[r * PIT + c];
        q[0] = q4.x; q[1] = q4.y; q[2] = q4.z; q[3] = q4.w;
        float* kk = &Ks[r * PIT + c];
        kk[0] = k4.x; kk[1] = k4.y; kk[2] = k4.z; kk[3] = k4.w;
        float* vv = &Vs[r * PIT + c];
        vv[0] = v4.x; vv[1] = v4.y; vv[2] = v4.z; vv[3] = v4.w;
    }
    __syncthreads();

    const int tr = tid >> 4, tc = tid & 15;
    float s4[4][4];
#pragma unroll
    for (int i = 0; i < 4; i++)
#pragma unroll
        for (int j = 0; j < 4; j++) s4[i][j] = 0.f;
#pragma unroll 8
    for (int k = 0; k < 64; k++) {
        float qv[4], kv[4];
#pragma unroll
        for (int i = 0; i < 4; i++) qv[i] = Qs[(tr * 4 + i) * PIT + k];
#pragma unroll
        for (int j = 0; j < 4; j++) kv[j] = Ks[(tc * 4 + j) * PIT + k];
#pragma unroll
        for (int i = 0; i < 4; i++)
#pragma unroll
            for (int j = 0; j < 4; j++) s4[i][j] += qv[i] * kv[j];
    }
    // scale + relative position bias: bias[query i][key j] = pos[(da*7+db)*7+dc], d* = a_j-a_i+3
#pragma unroll
    for (int i = 0; i < 4; i++) {
        int u1 = tr * 4 + i;
        float m = -1e30f;
#pragma unroll
        for (int j = 0; j < 4; j++) {
            int u2 = tc * 4 + j;
            int da = (u2 >> 4) - (u1 >> 4) + 3;
            int db = ((u2 >> 2) & 3) - ((u1 >> 2) & 3) + 3;
            int dc = (u2 & 3) - (u1 & 3) + 3;
            float v = s4[i][j] * 0.125f + ps[(da * 7 + db) * 7 + dc];
            s4[i][j] = v;
            m = fmaxf(m, v);
        }
        red[tc * 64 + u1] = m;
    }
    __syncthreads();
    if (tid < 64) {
        float m = red[tid];
#pragma unroll
        for (int t2 = 1; t2 < 16; t2++) m = fmaxf(m, red[t2 * 64 + tid]);
        rowm[tid] = m;
    }
    __syncthreads();
#pragma unroll
    for (int i = 0; i < 4; i++) {
        int u1 = tr * 4 + i;
        float mn = rowm[u1];
        float l = 0.f;
#pragma unroll
        for (int j = 0; j < 4; j++) {
            float p = __expf(s4[i][j] - mn);
            Ss[u1 * PIT + tc * 4 + j] = p;
            l += p;
        }
        red[tc * 64 + u1] = l;
    }
    __syncthreads();
    if (tid < 64) {
        float l = 0.f;
#pragma unroll
        for (int t2 = 0; t2 < 16; t2++) l += red[t2 * 64 + tid];
        rowl[tid] = l;
    }
    __syncthreads();

    float o[4][4];
#pragma unroll
    for (int i = 0; i < 4; i++)
#pragma unroll
        for (int j = 0; j < 4; j++) o[i][j] = 0.f;
#pragma unroll 8
    for (int k = 0; k < 64; k++) {
        float pv[4], vv[4];
#pragma unroll
        for (int i = 0; i < 4; i++) pv[i] = Ss[(tr * 4 + i) * PIT + k];
#pragma unroll
        for (int j = 0; j < 4; j++) vv[j] = Vs[k * PIT + tc * 4 + j];
#pragma unroll
        for (int i = 0; i < 4; i++)
#pragma unroll
            for (int j = 0; j < 4; j++) o[i][j] += pv[i] * vv[j];
    }
#pragma unroll
    for (int i = 0; i < 4; i++) {
        int u1 = tr * 4 + i;
        float inv = 1.f / rowl[u1];
        float4 ov = make_float4(o[i][0] * inv, o[i][1] * inv, o[i][2] * inv, o[i][3] * inv);
        *(float4*)&O[(size_t)rowIdx[u1] * CDIM + hoff + tc * 4] = ov;
    }
}

// ---------------------------------------------------------------------------
// Branch-2 attention: seq 24, head dim 64. grid (1152, 8), 192 threads.
// ---------------------------------------------------------------------------
__global__ __launch_bounds__(192)
void attn_small(const float* __restrict__ Q, const float* __restrict__ K,
                const float* __restrict__ V, float* __restrict__ O)
{
    __shared__ float Qs[24][PIT], Ks[24][PIT], Vs[24][PIT];
    __shared__ float Ss[24][28];

    const int tid = threadIdx.x;
    const int i2 = blockIdx.x, h = blockIdx.y;
    const size_t base = (size_t)i2 * 24;
    const int hoff = h * 64;

    for (int p = tid; p < 384; p += 192) {
        int r = p >> 4, c = (p & 15) << 2;
        size_t row = (base + r) * CDIM + hoff + c;
        float4 q4 = *(const float4*)&Q[row];
        Qs[r][c] = q4.x; Qs[r][c + 1] = q4.y; Qs[r][c + 2] = q4.z; Qs[r][c + 3] = q4.w;
        float4 k4 = *(const float4*)&K[row];
        Ks[r][c] = k4.x; Ks[r][c + 1] = k4.y; Ks[r][c + 2] = k4.z; Ks[r][c + 3] = k4.w;
        float4 v4 = *(const float4*)&V[row];
        Vs[r][c] = v4.x; Vs[r][c + 1] = v4.y; Vs[r][c + 2] = v4.z; Vs[r][c + 3] = v4.w;
    }
    __syncthreads();

    if (tid < 144) {
        int r = tid / 6, cg = tid % 6;
#pragma unroll
        for (int j = 0; j < 4; j++) {
            int c = cg * 4 + j;
            float acc = 0.f;
#pragma unroll 8
            for (int k = 0; k < 64; k++) acc += Qs[r][k] * Ks[c][k];
            Ss[r][c] = acc * 0.125f;
        }
    }
    __syncthreads();
    if (tid < 24) {
        float m = -1e30f;
#pragma unroll
        for (int k = 0; k < 24; k++) m = fmaxf(m, Ss[tid][k]);
        float l = 0.f;
        float e[24];
#pragma unroll
        for (int k = 0; k < 24; k++) { e[k] = __expf(Ss[tid][k] - m); l += e[k]; }
        float inv = 1.f / l;
#pragma unroll
        for (int k = 0; k < 24; k++) Ss[tid][k] = e[k] * inv;
    }
    __syncthreads();

    {
        int r = tid >> 3;            // 0..23
        int cb = tid & 7;            // 8 col groups of 8
        float acc[8];
#pragma unroll
        for (int j = 0; j < 8; j++) acc[j] = 0.f;
#pragma unroll
        for (int k = 0; k < 24; k++) {
            float p = Ss[r][k];
#pragma unroll
            for (int j = 0; j < 8; j++) acc[j] += p * Vs[k][cb * 8 + j];
        }
        float* Orow = &O[(base + r) * CDIM + hoff + cb * 8];
#pragma unroll
        for (int j = 0; j < 8; j++) Orow[j] = acc[j];
    }
}

// ---------------------------------------------------------------------------
extern "C" void kernel_launch(void* const* d_in, const int* in_sizes, int n_in,
                              void* d_out, int out_size)
{
    const float* x        = (const float*)d_in[0];
    const float* vq_w     = (const float*)d_in[1];
    const float* vq_b     = (const float*)d_in[2];
    const float* vk_w     = (const float*)d_in[3];
    const float* vk_b     = (const float*)d_in[4];
    const float* vv_w     = (const float*)d_in[5];
    const float* vv_b     = (const float*)d_in[6];
    const float* vo_w     = (const float*)d_in[7];
    const float* vo_b     = (const float*)d_in[8];
    const float* hq_w     = (const float*)d_in[9];
    const float* hq_b     = (const float*)d_in[10];
    const float* hk_w     = (const float*)d_in[11];
    const float* hk_b     = (const float*)d_in[12];
    const float* hv_w     = (const float*)d_in[13];
    const float* hv_b     = (const float*)d_in[14];
    const float* ho_w     = (const float*)d_in[15];
    const float* ho_b     = (const float*)d_in[16];
    const float* qkv_w    = (const float*)d_in[17];
    const float* wout_w   = (const float*)d_in[18];
    const float* wout_b   = (const float*)d_in[19];
    const float* pos      = (const float*)d_in[20];
    float* out = (float*)d_out;

    float *X, *QKV;
    cudaGetSymbolAddress((void**)&X, g_X);
    cudaGetSymbolAddress((void**)&QKV, g_QKV);
    float* Qb = QKV;
    float* Kb = QKV + (size_t)TTOK * CDIM;
    float* Vb = QKV + 2 * (size_t)TTOK * CDIM;

    // Idempotent, non-stream API: safe every call (no static guards allowed).
    cudaFuncSetAttribute(attn_long, cudaFuncAttributeMaxDynamicSharedMemorySize, 80000);
    cudaFuncSetAttribute(attn_win,  cudaFuncAttributeMaxDynamicSharedMemorySize, 80000);

    const int SM_LONG = (4 * 64 * PIT + 3 * 64 + 16 * 64) * 4;
    const int SM_WIN  = (4 * 64 * PIT + 2 * 64 + 16 * 64 + 343) * 4;

    dim3 tb(32, 32);
    dim3 gg(4, 216);   // sgemm grid for N=512  (M=27648 -> 216 row tiles)
    dim3 gq(12, 216);  // sgemm grid for N=1536

    // ---- Branch 1 (raw-reshape batches: 48 x seq 576) ----
    transpose_gather<<<dim3(18, 16, 48), tb>>>(x, X, 576, 294912);
    sgemm<<<gg, 256>>>(X, vq_w, vq_b, Qb, TTOK, CDIM, CDIM, 0);
    sgemm<<<gg, 256>>>(X, vk_w, vk_b, Kb, TTOK, CDIM, CDIM, 0);
    sgemm<<<gg, 256>>>(X, vv_w, vv_b, Vb, TTOK, CDIM, CDIM, 0);
    attn_long<<<dim3(9, 8, 48), 256, SM_LONG>>>(Qb, Kb, Vb, X, 9);
    sgemm<<<gg, 256>>>(X, vo_w, vo_b, out, TTOK, CDIM, CDIM, 0);

    // ---- Branch 2 (raw-reshape batches: 1152 x seq 24) ----
    transpose_gather<<<dim3(1, 16, 1152), tb>>>(x, X, 24, 12288);
    sgemm<<<gg, 256>>>(X, hq_w, hq_b, Qb, TTOK, CDIM, CDIM, 0);
    sgemm<<<gg, 256>>>(X, hk_w, hk_b, Kb, TTOK, CDIM, CDIM, 0);
    sgemm<<<gg, 256>>>(X, hv_w, hv_b, Vb, TTOK, CDIM, CDIM, 0);
    attn_small<<<dim3(1152, 8), 192>>>(Qb, Kb, Vb, X);
    sgemm<<<gg, 256>>>(X, ho_w, ho_b, out, TTOK, CDIM, CDIM, 1);

    // ---- Branch 3 (windowed: 216 windows x 64 tokens, 2 batches) ----
    transpose_gather<<<dim3(432, 16, 2), tb>>>(x, X, 13824, 7077888);
    sgemm<<<gq, 256>>>(X, qkv_w, (const float*)nullptr, QKV, TTOK, 3 * CDIM, CDIM, 0);
    attn_win<<<dim3(216, 8, 2), 256, SM_WIN>>>(QKV, X, pos);
    sgemm<<<gg, 256>>>(X, wout_w, wout_b, out, TTOK, CDIM, CDIM, 1);
}